// round 14
// baseline (speedup 1.0000x reference)
#include <cuda_runtime.h>
#include <math.h>
#include <cstdint>

#define BB 2
#define NN 2048
#define DD 512
#define HH 8
#define HDIM 64
#define RR 64
#define WW 129          // window width = 2R+1
#define MM (BB*NN)      // 4096 rows

// ------------------------- scratch (no cudaMalloc allowed) -------------------------
__device__ float g_x  [BB*NN*DD];       // LN1 output
__device__ float g_rep[BB*NN*DD];       // normalized LN1 output
__device__ float g_q  [BB*HH*NN*HDIM];
__device__ float g_k  [BB*HH*NN*HDIM];
__device__ float g_v  [BB*HH*NN*HDIM];
__device__ float g_corr[BB*132*NN];     // transposed: [b][off][i]
__device__ float g_upd[BB*NN*DD];
__device__ float g_n2 [BB*NN*DD];       // nodes after attention residual
__device__ float g_y  [BB*NN*DD];       // LN2 output
__device__ float g_h  [BB*NN*2*DD];     // MLP hidden

// ------------------------- packed f32x2 helpers -------------------------
__device__ __forceinline__ unsigned long long pack2(float x, float y){
    unsigned long long r;
    asm("mov.b64 %0, {%1, %2};" : "=l"(r) : "f"(x), "f"(y));
    return r;
}
__device__ __forceinline__ void fma2(unsigned long long &d, unsigned long long a, unsigned long long b){
    asm("fma.rn.f32x2 %0, %1, %2, %0;" : "+l"(d) : "l"(a), "l"(b));
}
__device__ __forceinline__ float2 unpack2(unsigned long long v){
    float2 r;
    asm("mov.b64 {%0, %1}, %2;" : "=f"(r.x), "=f"(r.y) : "l"(v));
    return r;
}

// ------------------------- block reduce (sum, sum) -------------------------
__device__ __forceinline__ float2 block_reduce2(float a, float b){
    __shared__ float sa[8], sb[8];
    #pragma unroll
    for (int o=16;o>0;o>>=1){
        a += __shfl_xor_sync(0xffffffffu, a, o);
        b += __shfl_xor_sync(0xffffffffu, b, o);
    }
    __syncthreads();                       // protect reuse of sa/sb
    int w = threadIdx.x >> 5;
    if ((threadIdx.x & 31) == 0){ sa[w] = a; sb[w] = b; }
    __syncthreads();
    float ta = 0.f, tb = 0.f;
    #pragma unroll
    for (int i=0;i<8;i++){ ta += sa[i]; tb += sb[i]; }
    return make_float2(ta, tb);
}

// ------------------------- LayerNorm (optionally + L2-normalized rep) -------------------------
__global__ void __launch_bounds__(256) ln_kernel(
    const float* __restrict__ in, const float* __restrict__ gw, const float* __restrict__ bw,
    float* __restrict__ xo, float* __restrict__ rep, int with_rep)
{
    int row = blockIdx.x, t = threadIdx.x;
    const float* p = in + (size_t)row*DD;
    float2 v = *(const float2*)(p + t*2);
    float2 r = block_reduce2(v.x + v.y, v.x*v.x + v.y*v.y);
    float mean = r.x * (1.f/DD);
    float var  = r.y * (1.f/DD) - mean*mean;
    float inv  = rsqrtf(var + 1e-5f);
    float2 g2 = *(const float2*)(gw + t*2);
    float2 b2 = *(const float2*)(bw + t*2);
    float x0 = (v.x - mean)*inv*g2.x + b2.x;
    float x1 = (v.y - mean)*inv*g2.y + b2.y;
    *(float2*)(xo + (size_t)row*DD + t*2) = make_float2(x0, x1);
    if (with_rep){
        float2 s2 = block_reduce2(x0*x0 + x1*x1, 0.f);
        float rn = 1.f / fmaxf(sqrtf(s2.x), 1e-12f);
        *(float2*)(rep + (size_t)row*DD + t*2) = make_float2(x0*rn, x1*rn);
    }
}

// ------------------------- SGEMM 128x128x8, double buffered, f32x2 FMA -------------------------
// MODE 0: QKV scatter (bias add, split into q/k/v [B,H,N,64])
// MODE 1: out = A@W + bias + res
// MODE 2: out = gelu_exact(A@W + bias)
template<int MODE>
__global__ void __launch_bounds__(256) sgemm_kernel(
    const float* __restrict__ A, const float* __restrict__ W,
    const float* __restrict__ bias, const float* __restrict__ res,
    float* __restrict__ o0, float* __restrict__ o1, float* __restrict__ o2,
    int M, int Nn, int K)
{
    __shared__ float As[2][8][128];
    __shared__ float Bs[2][8][128];
    int m0 = blockIdx.y * 128, n0 = blockIdx.x * 128;
    int t = threadIdx.x;
    int arow = t >> 1, acol = (t & 1) * 4;    // A tile loader
    int brow = t >> 5, bcol = (t & 31) * 4;   // B tile loader
    const float* Ag = A + (size_t)(m0 + arow)*K + acol;
    const float* Bg = W + (size_t)brow*Nn + n0 + bcol;

    float4 ra = *(const float4*)Ag;
    float4 rb = *(const float4*)Bg;
    As[0][acol+0][arow]=ra.x; As[0][acol+1][arow]=ra.y;
    As[0][acol+2][arow]=ra.z; As[0][acol+3][arow]=ra.w;
    *(float4*)&Bs[0][brow][bcol] = rb;
    __syncthreads();

    int ry = t >> 4, cx = t & 15;
    unsigned long long acc[8][4];
    #pragma unroll
    for (int i=0;i<8;i++)
        #pragma unroll
        for (int jp=0;jp<4;jp++) acc[i][jp] = 0ULL;

    int nT = K >> 3;
    int buf = 0;
    for (int tt = 1; tt <= nT; ++tt){
        if (tt < nT){
            ra = *(const float4*)(Ag + tt*8);
            rb = *(const float4*)(Bg + (size_t)tt*8*Nn);
        }
        #pragma unroll
        for (int k=0;k<8;k++){
            float4 a0 = *(const float4*)&As[buf][k][ry*4];
            float4 a1 = *(const float4*)&As[buf][k][64 + ry*4];
            float4 b0 = *(const float4*)&Bs[buf][k][cx*4];
            float4 b1 = *(const float4*)&Bs[buf][k][64 + cx*4];
            unsigned long long bp0 = pack2(b0.x,b0.y), bp1 = pack2(b0.z,b0.w);
            unsigned long long bp2 = pack2(b1.x,b1.y), bp3 = pack2(b1.z,b1.w);
            float av[8] = {a0.x,a0.y,a0.z,a0.w,a1.x,a1.y,a1.z,a1.w};
            #pragma unroll
            for (int i=0;i<8;i++){
                unsigned long long ad = pack2(av[i], av[i]);
                fma2(acc[i][0], ad, bp0);
                fma2(acc[i][1], ad, bp1);
                fma2(acc[i][2], ad, bp2);
                fma2(acc[i][3], ad, bp3);
            }
        }
        if (tt < nT){
            buf ^= 1;
            As[buf][acol+0][arow]=ra.x; As[buf][acol+1][arow]=ra.y;
            As[buf][acol+2][arow]=ra.z; As[buf][acol+3][arow]=ra.w;
            *(float4*)&Bs[buf][brow][bcol] = rb;
            __syncthreads();
        }
    }

    // epilogue
    #pragma unroll
    for (int i=0;i<8;i++){
        int r = m0 + ((i < 4) ? (ry*4 + i) : (64 + ry*4 + (i-4)));
        #pragma unroll
        for (int jp=0;jp<4;jp++){
            float2 vv = unpack2(acc[i][jp]);
            int c0 = n0 + ((jp < 2) ? (cx*4 + jp*2) : (64 + cx*4 + (jp-2)*2));
            #pragma unroll
            for (int e=0;e<2;e++){
                float val = (e==0 ? vv.x : vv.y);
                int c = c0 + e;
                val += bias[c];
                if (MODE == 0){
                    int which = c >> 9;
                    int hh = (c >> 6) & 7;
                    int hd = c & 63;
                    int bb = r >> 11;        // N = 2048
                    int nn = r & 2047;
                    float* dst = (which == 0) ? o0 : ((which == 1) ? o1 : o2);
                    dst[(((size_t)(bb*HH + hh))*NN + nn)*HDIM + hd] = val;
                } else if (MODE == 1){
                    o0[(size_t)r*Nn + c] = val + res[(size_t)r*Nn + c];
                } else {
                    o0[(size_t)r*Nn + c] = 0.5f*val*(1.f + erff(val*0.70710678118654752f));
                }
            }
        }
    }
}

// ------------------------- banded rep-correlation: corr[b][off][i] = rep_i . rep_{i-R+off} -------------------------
__global__ void __launch_bounds__(256) corr_kernel(const float* __restrict__ rep, float* __restrict__ corr)
{
    __shared__ float sQ[32*36];
    __shared__ float sK[160*36];
    int b = blockIdx.x >> 6, tile = blockIdx.x & 63;
    int i0 = tile*32, j0 = i0 - RR;
    int t = threadIdx.x;
    int qi = t & 31, off0 = t >> 5;
    float acc[17];
    #pragma unroll
    for (int kk=0;kk<17;kk++) acc[kk] = 0.f;
    const float* rbase = rep + (size_t)b*NN*DD;

    for (int ch=0; ch<16; ++ch){
        int c0 = ch*32;
        {   // Q chunk: 32x32
            int row = t >> 3, c4 = (t & 7)*4;
            *(float4*)(sQ + row*36 + c4) = *(const float4*)(rbase + (size_t)(i0+row)*DD + c0 + c4);
        }
        #pragma unroll
        for (int s=0;s<5;s++){   // K chunk: 160x32
            int idx = t + s*256;
            int row = idx >> 3, c4 = (idx & 7)*4;
            int j = j0 + row;
            float4 val = make_float4(0.f,0.f,0.f,0.f);
            if (j >= 0 && j < NN) val = *(const float4*)(rbase + (size_t)j*DD + c0 + c4);
            *(float4*)(sK + row*36 + c4) = val;
        }
        __syncthreads();
        float4 qreg[8];
        #pragma unroll
        for (int c=0;c<8;c++) qreg[c] = *(const float4*)(sQ + qi*36 + c*4);
        #pragma unroll
        for (int kk=0;kk<17;kk++){
            int off = off0 + 8*kk;
            if (off > 128) break;
            const float4* k4 = (const float4*)(sK + (qi+off)*36);
            float s = acc[kk];
            #pragma unroll
            for (int c=0;c<8;c++){
                float4 kv = k4[c];
                s += qreg[c].x*kv.x + qreg[c].y*kv.y + qreg[c].z*kv.z + qreg[c].w*kv.w;
            }
            acc[kk] = s;
        }
        __syncthreads();
    }
    int i = i0 + qi;
    #pragma unroll
    for (int kk=0;kk<17;kk++){
        int off = off0 + 8*kk;
        if (off > 128) break;
        int j = j0 + qi + off;
        if (j >= 0 && j < NN)
            corr[((size_t)b*132 + off)*NN + i] = acc[kk];
    }
}

// ------------------------- banded attention -------------------------
// block = (b, h, 32-query tile); keys window = 160 rows; dyn smem 73232 B
__global__ void __launch_bounds__(256) attn_kernel(
    const float* __restrict__ q, const float* __restrict__ k, const float* __restrict__ v,
    const float* __restrict__ corr, const float* __restrict__ rel_bias,
    const float* __restrict__ rep_scale, float* __restrict__ upd)
{
    extern __shared__ float sm[];
    float* sKV   = sm;                 // 160*68
    float* sQ    = sm + 160*68;        // 32*68
    float* sS    = sQ + 32*68;         // 32*160
    float* sBias = sS + 32*160;        // 132

    int blk = blockIdx.x;
    int tile = blk & 63, h = (blk >> 6) & 7, b = blk >> 9;
    int i0 = tile*32, j0 = i0 - RR;
    int t = threadIdx.x;
    float rs = rep_scale[h];

    if (t < WW) sBias[t] = rel_bias[(size_t)(NN-1+RR - t)*HH + h];

    const float* qbase = q + ((size_t)(b*HH + h)*NN)*HDIM;
    const float* kbase = k + ((size_t)(b*HH + h)*NN)*HDIM;
    const float* vbase = v + ((size_t)(b*HH + h)*NN)*HDIM;

    #pragma unroll
    for (int s=0;s<2;s++){   // Q: 32x64
        int idx = t + s*256;
        int row = idx >> 4, c4 = (idx & 15)*4;
        *(float4*)(sQ + row*68 + c4) = *(const float4*)(qbase + (size_t)(i0+row)*HDIM + c4);
    }
    #pragma unroll
    for (int s=0;s<10;s++){  // K: 160x64, zero-fill out of range
        int idx = t + s*256;
        int row = idx >> 4, c4 = (idx & 15)*4;
        int j = j0 + row;
        float4 val = make_float4(0.f,0.f,0.f,0.f);
        if (j >= 0 && j < NN) val = *(const float4*)(kbase + (size_t)j*HDIM + c4);
        *(float4*)(sKV + row*68 + c4) = val;
    }
    float ninf = -INFINITY;
    #pragma unroll
    for (int s=0;s<20;s++) sS[t + s*256] = ninf;
    __syncthreads();

    // ---- scores ----
    {
        int qi = t & 31, off0 = t >> 5;
        int i = i0 + qi;
        float4 qreg[16];
        #pragma unroll
        for (int c=0;c<16;c++) qreg[c] = *(const float4*)(sQ + qi*68 + c*4);
        #pragma unroll
        for (int kk=0;kk<17;kk++){
            int off = off0 + 8*kk;
            if (off > 128) break;
            int l = qi + off;
            int j = j0 + l;
            if (j >= 0 && j < NN){
                const float4* k4 = (const float4*)(sKV + l*68);
                float acc = 0.f;
                #pragma unroll
                for (int c=0;c<16;c++){
                    float4 kv = k4[c];
                    acc += qreg[c].x*kv.x + qreg[c].y*kv.y + qreg[c].z*kv.z + qreg[c].w*kv.w;
                }
                sS[qi*160 + l] = acc*0.125f
                               + rs * corr[((size_t)b*132 + off)*NN + i]
                               + sBias[off];
            }
        }
    }
    __syncthreads();

    // ---- softmax (8 warps x 4 rows) ----
    {
        int w = t >> 5, lane = t & 31;
        for (int r=0;r<4;r++){
            float* row = sS + (w*4 + r)*160;
            float m = -INFINITY;
            for (int e=lane;e<160;e+=32) m = fmaxf(m, row[e]);
            #pragma unroll
            for (int o=16;o>0;o>>=1) m = fmaxf(m, __shfl_xor_sync(0xffffffffu, m, o));
            float sum = 0.f;
            for (int e=lane;e<160;e+=32){
                float p = expf(row[e] - m);
                row[e] = p;
                sum += p;
            }
            #pragma unroll
            for (int o=16;o>0;o>>=1) sum += __shfl_xor_sync(0xffffffffu, sum, o);
            float inv = 1.f / sum;
            for (int e=lane;e<160;e+=32) row[e] *= inv;
        }
    }

    // ---- load V (reuse K buffer; safe: K reads finished before pre-softmax barrier) ----
    #pragma unroll
    for (int s=0;s<10;s++){
        int idx = t + s*256;
        int row = idx >> 4, c4 = (idx & 15)*4;
        int j = j0 + row;
        float4 val = make_float4(0.f,0.f,0.f,0.f);
        if (j >= 0 && j < NN) val = *(const float4*)(vbase + (size_t)j*HDIM + c4);
        *(float4*)(sKV + row*68 + c4) = val;
    }
    __syncthreads();

    // ---- attn @ V ----
    {
        int qi = t >> 3;
        int cb = (t & 7)*4;   // cols cb and cb+32 (conflict-free)
        const float* srow = sS + qi*160;
        float4 a0 = make_float4(0.f,0.f,0.f,0.f);
        float4 a1 = make_float4(0.f,0.f,0.f,0.f);
        for (int l = qi; l <= qi + 128; ++l){
            float p = srow[l];
            float4 v0 = *(const float4*)(sKV + l*68 + cb);
            float4 v1 = *(const float4*)(sKV + l*68 + cb + 32);
            a0.x += p*v0.x; a0.y += p*v0.y; a0.z += p*v0.z; a0.w += p*v0.w;
            a1.x += p*v1.x; a1.y += p*v1.y; a1.z += p*v1.z; a1.w += p*v1.w;
        }
        float* dst = upd + ((size_t)(b*NN + i0 + qi))*DD + h*HDIM + cb;
        *(float4*)dst        = a0;
        *(float4*)(dst + 32) = a1;
    }
}

// ------------------------- host launch -------------------------
extern "C" void kernel_launch(void* const* d_in, const int* in_sizes, int n_in,
                              void* d_out, int out_size)
{
    const float* nodes     = (const float*)d_in[0];
    const float* ln1_g     = (const float*)d_in[1];
    const float* ln1_b     = (const float*)d_in[2];
    const float* qkv_w     = (const float*)d_in[3];
    const float* qkv_b     = (const float*)d_in[4];
    const float* proj_w    = (const float*)d_in[5];
    const float* proj_b    = (const float*)d_in[6];
    const float* rep_scale = (const float*)d_in[7];
    const float* rel_bias  = (const float*)d_in[8];
    const float* ln2_g     = (const float*)d_in[9];
    const float* ln2_b     = (const float*)d_in[10];
    const float* mlp_w1    = (const float*)d_in[11];
    const float* mlp_b1    = (const float*)d_in[12];
    const float* mlp_w2    = (const float*)d_in[13];
    const float* mlp_b2    = (const float*)d_in[14];
    float* out = (float*)d_out;

    float *x, *rep, *q, *k, *v, *corr, *upd, *n2, *y, *hbuf;
    cudaGetSymbolAddress((void**)&x,    g_x);
    cudaGetSymbolAddress((void**)&rep,  g_rep);
    cudaGetSymbolAddress((void**)&q,    g_q);
    cudaGetSymbolAddress((void**)&k,    g_k);
    cudaGetSymbolAddress((void**)&v,    g_v);
    cudaGetSymbolAddress((void**)&corr, g_corr);
    cudaGetSymbolAddress((void**)&upd,  g_upd);
    cudaGetSymbolAddress((void**)&n2,   g_n2);
    cudaGetSymbolAddress((void**)&y,    g_y);
    cudaGetSymbolAddress((void**)&hbuf, g_h);

    const int ATT_SMEM = (160*68 + 32*68 + 32*160 + 132) * 4;   // 73232 B
    cudaFuncSetAttribute(attn_kernel, cudaFuncAttributeMaxDynamicSharedMemorySize, ATT_SMEM);

    // 1) LN1 + rep
    ln_kernel<<<MM, 256>>>(nodes, ln1_g, ln1_b, x, rep, 1);
    // 2) QKV GEMM (4096 x 1536 x 512) with scatter epilogue
    sgemm_kernel<0><<<dim3(1536/128, MM/128), 256>>>(x, qkv_w, qkv_b, nullptr, q, k, v, MM, 1536, DD);
    // 3) banded correlation
    corr_kernel<<<BB*(NN/32), 256>>>(rep, corr);
    // 4) banded attention
    attn_kernel<<<BB*HH*(NN/32), 256, ATT_SMEM>>>(q, k, v, corr, rel_bias, rep_scale, upd);
    // 5) proj + residual -> n2
    sgemm_kernel<1><<<dim3(512/128, MM/128), 256>>>(upd, proj_w, proj_b, nodes, n2, nullptr, nullptr, MM, DD, DD);
    // 6) LN2
    ln_kernel<<<MM, 256>>>(n2, ln2_g, ln2_b, y, nullptr, 0);
    // 7) MLP1 + exact GELU
    sgemm_kernel<2><<<dim3(1024/128, MM/128), 256>>>(y, mlp_w1, mlp_b1, nullptr, hbuf, nullptr, nullptr, MM, 2*DD, DD);
    // 8) MLP2 + residual -> out
    sgemm_kernel<1><<<dim3(512/128, MM/128), 256>>>(hbuf, mlp_w2, mlp_b2, n2, out, nullptr, nullptr, MM, DD, 2*DD);
}

// round 15
// speedup vs baseline: 1.5974x; 1.5974x over previous
#include <cuda_runtime.h>
#include <math.h>
#include <cstdint>

#define BB 2
#define NN 2048
#define DD 512
#define HH 8
#define HDIM 64
#define RR 64
#define WW 129          // window width = 2R+1
#define MM (BB*NN)      // 4096 rows

// ------------------------- scratch (no cudaMalloc allowed) -------------------------
__device__ float g_x  [BB*NN*DD];       // LN1 output
__device__ float g_rep[BB*NN*DD];       // normalized LN1 output
__device__ float g_q  [BB*HH*NN*HDIM];
__device__ float g_k  [BB*HH*NN*HDIM];
__device__ float g_v  [BB*HH*NN*HDIM];
__device__ float g_corr[BB*132*NN];     // transposed: [b][off][i]
__device__ float g_upd[BB*NN*DD];
__device__ float g_n2 [BB*NN*DD];       // nodes after attention residual
__device__ float g_y  [BB*NN*DD];       // LN2 output
__device__ float g_h  [BB*NN*2*DD];     // MLP hidden

// ------------------------- tf32 helpers -------------------------
__device__ __forceinline__ unsigned f2tf(float x){
    unsigned r; asm("cvt.rna.tf32.f32 %0, %1;" : "=r"(r) : "f"(x)); return r;
}
__device__ __forceinline__ uint4 cvt4(float4 v){
    uint4 u; u.x=f2tf(v.x); u.y=f2tf(v.y); u.z=f2tf(v.z); u.w=f2tf(v.w); return u;
}
__device__ __forceinline__ void mma_tf32(float* d, const unsigned* a, const unsigned* b){
    asm volatile("mma.sync.aligned.m16n8k8.row.col.f32.tf32.tf32.f32 "
        "{%0,%1,%2,%3}, {%4,%5,%6,%7}, {%8,%9}, {%0,%1,%2,%3};"
        : "+f"(d[0]), "+f"(d[1]), "+f"(d[2]), "+f"(d[3])
        : "r"(a[0]), "r"(a[1]), "r"(a[2]), "r"(a[3]), "r"(b[0]), "r"(b[1]));
}

// ------------------------- block reduce (sum, sum) -------------------------
__device__ __forceinline__ float2 block_reduce2(float a, float b){
    __shared__ float sa[8], sb[8];
    #pragma unroll
    for (int o=16;o>0;o>>=1){
        a += __shfl_xor_sync(0xffffffffu, a, o);
        b += __shfl_xor_sync(0xffffffffu, b, o);
    }
    __syncthreads();                       // protect reuse of sa/sb
    int w = threadIdx.x >> 5;
    if ((threadIdx.x & 31) == 0){ sa[w] = a; sb[w] = b; }
    __syncthreads();
    float ta = 0.f, tb = 0.f;
    #pragma unroll
    for (int i=0;i<8;i++){ ta += sa[i]; tb += sb[i]; }
    return make_float2(ta, tb);
}

// ------------------------- LayerNorm (optionally + L2-normalized rep) -------------------------
__global__ void __launch_bounds__(256) ln_kernel(
    const float* __restrict__ in, const float* __restrict__ gw, const float* __restrict__ bw,
    float* __restrict__ xo, float* __restrict__ rep, int with_rep)
{
    int row = blockIdx.x, t = threadIdx.x;
    const float* p = in + (size_t)row*DD;
    float2 v = *(const float2*)(p + t*2);
    float2 r = block_reduce2(v.x + v.y, v.x*v.x + v.y*v.y);
    float mean = r.x * (1.f/DD);
    float var  = r.y * (1.f/DD) - mean*mean;
    float inv  = rsqrtf(var + 1e-5f);
    float2 g2 = *(const float2*)(gw + t*2);
    float2 b2 = *(const float2*)(bw + t*2);
    float x0 = (v.x - mean)*inv*g2.x + b2.x;
    float x1 = (v.y - mean)*inv*g2.y + b2.y;
    *(float2*)(xo + (size_t)row*DD + t*2) = make_float2(x0, x1);
    if (with_rep){
        float2 s2 = block_reduce2(x0*x0 + x1*x1, 0.f);
        float rn = 1.f / fmaxf(sqrtf(s2.x), 1e-12f);
        *(float2*)(rep + (size_t)row*DD + t*2) = make_float2(x0*rn, x1*rn);
    }
}

// ------------------------- tf32 tensor-core GEMM: 128x128x16 tile -------------------------
// 8 warps in 2(m) x 4(n) grid; warp tile 64x32 = 4x4 of m16n8k8.
// MODE 0: QKV scatter (bias add, split into q/k/v [B,H,N,64])
// MODE 1: out = A@W + bias + res
// MODE 2: out = gelu_exact(A@W + bias)
template<int MODE>
__global__ void __launch_bounds__(256) tgemm_kernel(
    const float* __restrict__ A, const float* __restrict__ W,
    const float* __restrict__ bias, const float* __restrict__ res,
    float* __restrict__ o0, float* __restrict__ o1, float* __restrict__ o2,
    int M, int Nn, int K)
{
    __shared__ unsigned As[2][128][20];   // [m][k], pad 20: conflict-free frags
    __shared__ unsigned Bs[2][16][136];   // [k][n], pad 136: conflict-free frags

    int m0 = blockIdx.y * 128, n0 = blockIdx.x * 128;
    int t = threadIdx.x;
    int wid = t >> 5, lane = t & 31;
    int warpM = wid & 1, warpN = wid >> 1;
    int gr = lane >> 2, tg = lane & 3;

    // loader indexing: A tile 128x16 (512 float4), B tile 16x128 (512 float4)
    int a0row = t >> 2,        a0k = (t & 3) * 4;
    int a1row = (t + 256) >> 2, a1k = ((t + 256) & 3) * 4;
    int b0row = t >> 5,        b0c = (t & 31) * 4;
    int b1row = (t + 256) >> 5, b1c = ((t + 256) & 31) * 4;

    const float* Ag0 = A + (size_t)(m0 + a0row)*K + a0k;
    const float* Ag1 = A + (size_t)(m0 + a1row)*K + a1k;
    const float* Bg0 = W + (size_t)b0row*Nn + n0 + b0c;
    const float* Bg1 = W + (size_t)b1row*Nn + n0 + b1c;

    // preload chunk 0
    float4 ra0 = *(const float4*)Ag0;
    float4 ra1 = *(const float4*)Ag1;
    float4 rb0 = *(const float4*)Bg0;
    float4 rb1 = *(const float4*)Bg1;
    *(uint4*)&As[0][a0row][a0k] = cvt4(ra0);
    *(uint4*)&As[0][a1row][a1k] = cvt4(ra1);
    *(uint4*)&Bs[0][b0row][b0c] = cvt4(rb0);
    *(uint4*)&Bs[0][b1row][b1c] = cvt4(rb1);
    __syncthreads();

    float acc[4][4][4];
    #pragma unroll
    for (int mt=0;mt<4;mt++)
        #pragma unroll
        for (int nt=0;nt<4;nt++)
            #pragma unroll
            for (int e=0;e<4;e++) acc[mt][nt][e] = 0.f;

    int nT = K >> 4;   // chunks of 16
    int buf = 0;
    for (int tt = 1; tt <= nT; ++tt){
        if (tt < nT){
            ra0 = *(const float4*)(Ag0 + tt*16);
            ra1 = *(const float4*)(Ag1 + tt*16);
            rb0 = *(const float4*)(Bg0 + (size_t)tt*16*Nn);
            rb1 = *(const float4*)(Bg1 + (size_t)tt*16*Nn);
        }
        #pragma unroll
        for (int ks=0; ks<2; ++ks){
            int k8 = ks*8;
            unsigned af[4][4], bf[4][2];
            #pragma unroll
            for (int mt=0;mt<4;mt++){
                int m = warpM*64 + mt*16 + gr;
                af[mt][0] = As[buf][m  ][k8+tg];
                af[mt][1] = As[buf][m+8][k8+tg];
                af[mt][2] = As[buf][m  ][k8+tg+4];
                af[mt][3] = As[buf][m+8][k8+tg+4];
            }
            #pragma unroll
            for (int nt=0;nt<4;nt++){
                int n = warpN*32 + nt*8 + gr;
                bf[nt][0] = Bs[buf][k8+tg  ][n];
                bf[nt][1] = Bs[buf][k8+tg+4][n];
            }
            #pragma unroll
            for (int mt=0;mt<4;mt++)
                #pragma unroll
                for (int nt=0;nt<4;nt++)
                    mma_tf32(acc[mt][nt], af[mt], bf[nt]);
        }
        if (tt < nT){
            buf ^= 1;
            *(uint4*)&As[buf][a0row][a0k] = cvt4(ra0);
            *(uint4*)&As[buf][a1row][a1k] = cvt4(ra1);
            *(uint4*)&Bs[buf][b0row][b0c] = cvt4(rb0);
            *(uint4*)&Bs[buf][b1row][b1c] = cvt4(rb1);
            __syncthreads();
        }
    }

    // ---- epilogue ----
    #pragma unroll
    for (int mt=0;mt<4;mt++){
        #pragma unroll
        for (int nt=0;nt<4;nt++){
            int r0 = m0 + warpM*64 + mt*16 + gr;
            int c0 = n0 + warpN*32 + nt*8 + 2*tg;   // even
            float2 bia = *(const float2*)(bias + c0);
            #pragma unroll
            for (int half=0; half<2; ++half){
                int r = r0 + half*8;
                float v0 = acc[mt][nt][half*2+0] + bia.x;
                float v1 = acc[mt][nt][half*2+1] + bia.y;
                if (MODE == 0){
                    int which = c0 >> 9;
                    int hh = (c0 >> 6) & 7;
                    int hd = c0 & 63;
                    int bb = r >> 11;
                    int nn = r & 2047;
                    float* dst = (which == 0) ? o0 : ((which == 1) ? o1 : o2);
                    *(float2*)&dst[(((size_t)(bb*HH + hh))*NN + nn)*HDIM + hd] = make_float2(v0, v1);
                } else if (MODE == 1){
                    float2 rr = *(const float2*)(res + (size_t)r*Nn + c0);
                    *(float2*)&o0[(size_t)r*Nn + c0] = make_float2(v0 + rr.x, v1 + rr.y);
                } else {
                    float g0 = 0.5f*v0*(1.f + erff(v0*0.70710678118654752f));
                    float g1 = 0.5f*v1*(1.f + erff(v1*0.70710678118654752f));
                    *(float2*)&o0[(size_t)r*Nn + c0] = make_float2(g0, g1);
                }
            }
        }
    }
}

// ------------------------- banded rep-correlation: corr[b][off][i] = rep_i . rep_{i-R+off} -------------------------
__global__ void __launch_bounds__(256) corr_kernel(const float* __restrict__ rep, float* __restrict__ corr)
{
    __shared__ float sQ[32*36];
    __shared__ float sK[160*36];
    int b = blockIdx.x >> 6, tile = blockIdx.x & 63;
    int i0 = tile*32, j0 = i0 - RR;
    int t = threadIdx.x;
    int qi = t & 31, off0 = t >> 5;
    float acc[17];
    #pragma unroll
    for (int kk=0;kk<17;kk++) acc[kk] = 0.f;
    const float* rbase = rep + (size_t)b*NN*DD;

    for (int ch=0; ch<16; ++ch){
        int c0 = ch*32;
        {   // Q chunk: 32x32
            int row = t >> 3, c4 = (t & 7)*4;
            *(float4*)(sQ + row*36 + c4) = *(const float4*)(rbase + (size_t)(i0+row)*DD + c0 + c4);
        }
        #pragma unroll
        for (int s=0;s<5;s++){   // K chunk: 160x32
            int idx = t + s*256;
            int row = idx >> 3, c4 = (idx & 7)*4;
            int j = j0 + row;
            float4 val = make_float4(0.f,0.f,0.f,0.f);
            if (j >= 0 && j < NN) val = *(const float4*)(rbase + (size_t)j*DD + c0 + c4);
            *(float4*)(sK + row*36 + c4) = val;
        }
        __syncthreads();
        float4 qreg[8];
        #pragma unroll
        for (int c=0;c<8;c++) qreg[c] = *(const float4*)(sQ + qi*36 + c*4);
        #pragma unroll
        for (int kk=0;kk<17;kk++){
            int off = off0 + 8*kk;
            if (off > 128) break;
            const float4* k4 = (const float4*)(sK + (qi+off)*36);
            float s = acc[kk];
            #pragma unroll
            for (int c=0;c<8;c++){
                float4 kv = k4[c];
                s += qreg[c].x*kv.x + qreg[c].y*kv.y + qreg[c].z*kv.z + qreg[c].w*kv.w;
            }
            acc[kk] = s;
        }
        __syncthreads();
    }
    int i = i0 + qi;
    #pragma unroll
    for (int kk=0;kk<17;kk++){
        int off = off0 + 8*kk;
        if (off > 128) break;
        int j = j0 + qi + off;
        if (j >= 0 && j < NN)
            corr[((size_t)b*132 + off)*NN + i] = acc[kk];
    }
}

// ------------------------- banded attention -------------------------
// block = (b, h, 32-query tile); keys window = 160 rows; dyn smem 73232 B
__global__ void __launch_bounds__(256) attn_kernel(
    const float* __restrict__ q, const float* __restrict__ k, const float* __restrict__ v,
    const float* __restrict__ corr, const float* __restrict__ rel_bias,
    const float* __restrict__ rep_scale, float* __restrict__ upd)
{
    extern __shared__ float sm[];
    float* sKV   = sm;                 // 160*68
    float* sQ    = sm + 160*68;        // 32*68
    float* sS    = sQ + 32*68;         // 32*160
    float* sBias = sS + 32*160;        // 132

    int blk = blockIdx.x;
    int tile = blk & 63, h = (blk >> 6) & 7, b = blk >> 9;
    int i0 = tile*32, j0 = i0 - RR;
    int t = threadIdx.x;
    float rs = rep_scale[h];

    if (t < WW) sBias[t] = rel_bias[(size_t)(NN-1+RR - t)*HH + h];

    const float* qbase = q + ((size_t)(b*HH + h)*NN)*HDIM;
    const float* kbase = k + ((size_t)(b*HH + h)*NN)*HDIM;
    const float* vbase = v + ((size_t)(b*HH + h)*NN)*HDIM;

    #pragma unroll
    for (int s=0;s<2;s++){   // Q: 32x64
        int idx = t + s*256;
        int row = idx >> 4, c4 = (idx & 15)*4;
        *(float4*)(sQ + row*68 + c4) = *(const float4*)(qbase + (size_t)(i0+row)*HDIM + c4);
    }
    #pragma unroll
    for (int s=0;s<10;s++){  // K: 160x64, zero-fill out of range
        int idx = t + s*256;
        int row = idx >> 4, c4 = (idx & 15)*4;
        int j = j0 + row;
        float4 val = make_float4(0.f,0.f,0.f,0.f);
        if (j >= 0 && j < NN) val = *(const float4*)(kbase + (size_t)j*HDIM + c4);
        *(float4*)(sKV + row*68 + c4) = val;
    }
    float ninf = -INFINITY;
    #pragma unroll
    for (int s=0;s<20;s++) sS[t + s*256] = ninf;
    __syncthreads();

    // ---- scores ----
    {
        int qi = t & 31, off0 = t >> 5;
        int i = i0 + qi;
        float4 qreg[16];
        #pragma unroll
        for (int c=0;c<16;c++) qreg[c] = *(const float4*)(sQ + qi*68 + c*4);
        #pragma unroll
        for (int kk=0;kk<17;kk++){
            int off = off0 + 8*kk;
            if (off > 128) break;
            int l = qi + off;
            int j = j0 + l;
            if (j >= 0 && j < NN){
                const float4* k4 = (const float4*)(sKV + l*68);
                float acc = 0.f;
                #pragma unroll
                for (int c=0;c<16;c++){
                    float4 kv = k4[c];
                    acc += qreg[c].x*kv.x + qreg[c].y*kv.y + qreg[c].z*kv.z + qreg[c].w*kv.w;
                }
                sS[qi*160 + l] = acc*0.125f
                               + rs * corr[((size_t)b*132 + off)*NN + i]
                               + sBias[off];
            }
        }
    }
    __syncthreads();

    // ---- softmax (8 warps x 4 rows) ----
    {
        int w = t >> 5, lane = t & 31;
        for (int r=0;r<4;r++){
            float* row = sS + (w*4 + r)*160;
            float m = -INFINITY;
            for (int e=lane;e<160;e+=32) m = fmaxf(m, row[e]);
            #pragma unroll
            for (int o=16;o>0;o>>=1) m = fmaxf(m, __shfl_xor_sync(0xffffffffu, m, o));
            float sum = 0.f;
            for (int e=lane;e<160;e+=32){
                float p = expf(row[e] - m);
                row[e] = p;
                sum += p;
            }
            #pragma unroll
            for (int o=16;o>0;o>>=1) sum += __shfl_xor_sync(0xffffffffu, sum, o);
            float inv = 1.f / sum;
            for (int e=lane;e<160;e+=32) row[e] *= inv;
        }
    }

    // ---- load V (reuse K buffer; safe: K reads finished before pre-softmax barrier) ----
    #pragma unroll
    for (int s=0;s<10;s++){
        int idx = t + s*256;
        int row = idx >> 4, c4 = (idx & 15)*4;
        int j = j0 + row;
        float4 val = make_float4(0.f,0.f,0.f,0.f);
        if (j >= 0 && j < NN) val = *(const float4*)(vbase + (size_t)j*HDIM + c4);
        *(float4*)(sKV + row*68 + c4) = val;
    }
    __syncthreads();

    // ---- attn @ V ----
    {
        int qi = t >> 3;
        int cb = (t & 7)*4;   // cols cb and cb+32 (conflict-free)
        const float* srow = sS + qi*160;
        float4 a0 = make_float4(0.f,0.f,0.f,0.f);
        float4 a1 = make_float4(0.f,0.f,0.f,0.f);
        for (int l = qi; l <= qi + 128; ++l){
            float p = srow[l];
            float4 v0 = *(const float4*)(sKV + l*68 + cb);
            float4 v1 = *(const float4*)(sKV + l*68 + cb + 32);
            a0.x += p*v0.x; a0.y += p*v0.y; a0.z += p*v0.z; a0.w += p*v0.w;
            a1.x += p*v1.x; a1.y += p*v1.y; a1.z += p*v1.z; a1.w += p*v1.w;
        }
        float* dst = upd + ((size_t)(b*NN + i0 + qi))*DD + h*HDIM + cb;
        *(float4*)dst        = a0;
        *(float4*)(dst + 32) = a1;
    }
}

// ------------------------- host launch -------------------------
extern "C" void kernel_launch(void* const* d_in, const int* in_sizes, int n_in,
                              void* d_out, int out_size)
{
    const float* nodes     = (const float*)d_in[0];
    const float* ln1_g     = (const float*)d_in[1];
    const float* ln1_b     = (const float*)d_in[2];
    const float* qkv_w     = (const float*)d_in[3];
    const float* qkv_b     = (const float*)d_in[4];
    const float* proj_w    = (const float*)d_in[5];
    const float* proj_b    = (const float*)d_in[6];
    const float* rep_scale = (const float*)d_in[7];
    const float* rel_bias  = (const float*)d_in[8];
    const float* ln2_g     = (const float*)d_in[9];
    const float* ln2_b     = (const float*)d_in[10];
    const float* mlp_w1    = (const float*)d_in[11];
    const float* mlp_b1    = (const float*)d_in[12];
    const float* mlp_w2    = (const float*)d_in[13];
    const float* mlp_b2    = (const float*)d_in[14];
    float* out = (float*)d_out;

    float *x, *rep, *q, *k, *v, *corr, *upd, *n2, *y, *hbuf;
    cudaGetSymbolAddress((void**)&x,    g_x);
    cudaGetSymbolAddress((void**)&rep,  g_rep);
    cudaGetSymbolAddress((void**)&q,    g_q);
    cudaGetSymbolAddress((void**)&k,    g_k);
    cudaGetSymbolAddress((void**)&v,    g_v);
    cudaGetSymbolAddress((void**)&corr, g_corr);
    cudaGetSymbolAddress((void**)&upd,  g_upd);
    cudaGetSymbolAddress((void**)&n2,   g_n2);
    cudaGetSymbolAddress((void**)&y,    g_y);
    cudaGetSymbolAddress((void**)&hbuf, g_h);

    const int ATT_SMEM = (160*68 + 32*68 + 32*160 + 132) * 4;   // 73232 B
    cudaFuncSetAttribute(attn_kernel, cudaFuncAttributeMaxDynamicSharedMemorySize, ATT_SMEM);

    // 1) LN1 + rep
    ln_kernel<<<MM, 256>>>(nodes, ln1_g, ln1_b, x, rep, 1);
    // 2) QKV GEMM (4096 x 1536 x 512) with scatter epilogue  [tf32 tensor core]
    tgemm_kernel<0><<<dim3(1536/128, MM/128), 256>>>(x, qkv_w, qkv_b, nullptr, q, k, v, MM, 1536, DD);
    // 3) banded correlation
    corr_kernel<<<BB*(NN/32), 256>>>(rep, corr);
    // 4) banded attention
    attn_kernel<<<BB*HH*(NN/32), 256, ATT_SMEM>>>(q, k, v, corr, rel_bias, rep_scale, upd);
    // 5) proj + residual -> n2
    tgemm_kernel<1><<<dim3(512/128, MM/128), 256>>>(upd, proj_w, proj_b, nodes, n2, nullptr, nullptr, MM, DD, DD);
    // 6) LN2
    ln_kernel<<<MM, 256>>>(n2, ln2_g, ln2_b, y, nullptr, 0);
    // 7) MLP1 + exact GELU
    tgemm_kernel<2><<<dim3(1024/128, MM/128), 256>>>(y, mlp_w1, mlp_b1, nullptr, hbuf, nullptr, nullptr, MM, 2*DD, DD);
    // 8) MLP2 + residual -> out
    tgemm_kernel<1><<<dim3(512/128, MM/128), 256>>>(hbuf, mlp_w2, mlp_b2, n2, out, nullptr, nullptr, MM, DD, 2*DD);
}

// round 16
// speedup vs baseline: 1.5988x; 1.0009x over previous
#include <cuda_runtime.h>
#include <math.h>
#include <cstdint>

#define BB 2
#define NN 2048
#define DD 512
#define HH 8
#define HDIM 64
#define RR 64
#define WW 129          // window width = 2R+1
#define MM (BB*NN)      // 4096 rows

// ------------------------- scratch (no cudaMalloc allowed) -------------------------
__device__ float g_x  [BB*NN*DD];       // LN1 output
__device__ float g_rep[BB*NN*DD];       // normalized LN1 output
__device__ float g_q  [BB*HH*NN*HDIM];
__device__ float g_k  [BB*HH*NN*HDIM];
__device__ float g_v  [BB*HH*NN*HDIM];
__device__ float g_corr[BB*132*NN];     // transposed: [b][off][i]
__device__ float g_upd[BB*NN*DD];
__device__ float g_n2 [BB*NN*DD];       // nodes after attention residual
__device__ float g_y  [BB*NN*DD];       // LN2 output
__device__ float g_h  [BB*NN*2*DD];     // MLP hidden

// ------------------------- tf32 helpers -------------------------
__device__ __forceinline__ unsigned f2tf(float x){
    unsigned r; asm("cvt.rna.tf32.f32 %0, %1;" : "=r"(r) : "f"(x)); return r;
}
__device__ __forceinline__ uint4 cvt4(float4 v){
    uint4 u; u.x=f2tf(v.x); u.y=f2tf(v.y); u.z=f2tf(v.z); u.w=f2tf(v.w); return u;
}
__device__ __forceinline__ void mma_tf32(float* d, const unsigned* a, const unsigned* b){
    asm volatile("mma.sync.aligned.m16n8k8.row.col.f32.tf32.tf32.f32 "
        "{%0,%1,%2,%3}, {%4,%5,%6,%7}, {%8,%9}, {%0,%1,%2,%3};"
        : "+f"(d[0]), "+f"(d[1]), "+f"(d[2]), "+f"(d[3])
        : "r"(a[0]), "r"(a[1]), "r"(a[2]), "r"(a[3]), "r"(b[0]), "r"(b[1]));
}

// ------------------------- block reduce (sum, sum) -------------------------
__device__ __forceinline__ float2 block_reduce2(float a, float b){
    __shared__ float sa[8], sb[8];
    #pragma unroll
    for (int o=16;o>0;o>>=1){
        a += __shfl_xor_sync(0xffffffffu, a, o);
        b += __shfl_xor_sync(0xffffffffu, b, o);
    }
    __syncthreads();                       // protect reuse of sa/sb
    int w = threadIdx.x >> 5;
    if ((threadIdx.x & 31) == 0){ sa[w] = a; sb[w] = b; }
    __syncthreads();
    float ta = 0.f, tb = 0.f;
    #pragma unroll
    for (int i=0;i<8;i++){ ta += sa[i]; tb += sb[i]; }
    return make_float2(ta, tb);
}

// ------------------------- LayerNorm (optionally + L2-normalized rep) -------------------------
__global__ void __launch_bounds__(256) ln_kernel(
    const float* __restrict__ in, const float* __restrict__ gw, const float* __restrict__ bw,
    float* __restrict__ xo, float* __restrict__ rep, int with_rep)
{
    int row = blockIdx.x, t = threadIdx.x;
    const float* p = in + (size_t)row*DD;
    float2 v = *(const float2*)(p + t*2);
    float2 r = block_reduce2(v.x + v.y, v.x*v.x + v.y*v.y);
    float mean = r.x * (1.f/DD);
    float var  = r.y * (1.f/DD) - mean*mean;
    float inv  = rsqrtf(var + 1e-5f);
    float2 g2 = *(const float2*)(gw + t*2);
    float2 b2 = *(const float2*)(bw + t*2);
    float x0 = (v.x - mean)*inv*g2.x + b2.x;
    float x1 = (v.y - mean)*inv*g2.y + b2.y;
    *(float2*)(xo + (size_t)row*DD + t*2) = make_float2(x0, x1);
    if (with_rep){
        float2 s2 = block_reduce2(x0*x0 + x1*x1, 0.f);
        float rn = 1.f / fmaxf(sqrtf(s2.x), 1e-12f);
        *(float2*)(rep + (size_t)row*DD + t*2) = make_float2(x0*rn, x1*rn);
    }
}

// ------------------------- tf32 tensor-core GEMM: 128x128x16 tile -------------------------
// 8 warps in 2(m) x 4(n) grid; warp tile 64x32 = 4x4 of m16n8k8.
// MODE 0: QKV scatter (bias add, split into q/k/v [B,H,N,64])
// MODE 1: out = A@W + bias + res
// MODE 2: out = gelu_exact(A@W + bias)
template<int MODE>
__global__ void __launch_bounds__(256) tgemm_kernel(
    const float* __restrict__ A, const float* __restrict__ W,
    const float* __restrict__ bias, const float* __restrict__ res,
    float* __restrict__ o0, float* __restrict__ o1, float* __restrict__ o2,
    int M, int Nn, int K)
{
    __shared__ unsigned As[2][128][20];   // [m][k], pad 20: conflict-free frags
    __shared__ unsigned Bs[2][16][136];   // [k][n], pad 136: conflict-free frags

    int m0 = blockIdx.y * 128, n0 = blockIdx.x * 128;
    int t = threadIdx.x;
    int wid = t >> 5, lane = t & 31;
    int warpM = wid & 1, warpN = wid >> 1;
    int gr = lane >> 2, tg = lane & 3;

    // loader indexing: A tile 128x16 (512 float4), B tile 16x128 (512 float4)
    int a0row = t >> 2,        a0k = (t & 3) * 4;
    int a1row = (t + 256) >> 2, a1k = ((t + 256) & 3) * 4;
    int b0row = t >> 5,        b0c = (t & 31) * 4;
    int b1row = (t + 256) >> 5, b1c = ((t + 256) & 31) * 4;

    const float* Ag0 = A + (size_t)(m0 + a0row)*K + a0k;
    const float* Ag1 = A + (size_t)(m0 + a1row)*K + a1k;
    const float* Bg0 = W + (size_t)b0row*Nn + n0 + b0c;
    const float* Bg1 = W + (size_t)b1row*Nn + n0 + b1c;

    // preload chunk 0
    float4 ra0 = *(const float4*)Ag0;
    float4 ra1 = *(const float4*)Ag1;
    float4 rb0 = *(const float4*)Bg0;
    float4 rb1 = *(const float4*)Bg1;
    *(uint4*)&As[0][a0row][a0k] = cvt4(ra0);
    *(uint4*)&As[0][a1row][a1k] = cvt4(ra1);
    *(uint4*)&Bs[0][b0row][b0c] = cvt4(rb0);
    *(uint4*)&Bs[0][b1row][b1c] = cvt4(rb1);
    __syncthreads();

    float acc[4][4][4];
    #pragma unroll
    for (int mt=0;mt<4;mt++)
        #pragma unroll
        for (int nt=0;nt<4;nt++)
            #pragma unroll
            for (int e=0;e<4;e++) acc[mt][nt][e] = 0.f;

    int nT = K >> 4;   // chunks of 16
    int buf = 0;
    for (int tt = 1; tt <= nT; ++tt){
        if (tt < nT){
            ra0 = *(const float4*)(Ag0 + tt*16);
            ra1 = *(const float4*)(Ag1 + tt*16);
            rb0 = *(const float4*)(Bg0 + (size_t)tt*16*Nn);
            rb1 = *(const float4*)(Bg1 + (size_t)tt*16*Nn);
        }
        #pragma unroll
        for (int ks=0; ks<2; ++ks){
            int k8 = ks*8;
            unsigned af[4][4], bf[4][2];
            #pragma unroll
            for (int mt=0;mt<4;mt++){
                int m = warpM*64 + mt*16 + gr;
                af[mt][0] = As[buf][m  ][k8+tg];
                af[mt][1] = As[buf][m+8][k8+tg];
                af[mt][2] = As[buf][m  ][k8+tg+4];
                af[mt][3] = As[buf][m+8][k8+tg+4];
            }
            #pragma unroll
            for (int nt=0;nt<4;nt++){
                int n = warpN*32 + nt*8 + gr;
                bf[nt][0] = Bs[buf][k8+tg  ][n];
                bf[nt][1] = Bs[buf][k8+tg+4][n];
            }
            #pragma unroll
            for (int mt=0;mt<4;mt++)
                #pragma unroll
                for (int nt=0;nt<4;nt++)
                    mma_tf32(acc[mt][nt], af[mt], bf[nt]);
        }
        if (tt < nT){
            buf ^= 1;
            *(uint4*)&As[buf][a0row][a0k] = cvt4(ra0);
            *(uint4*)&As[buf][a1row][a1k] = cvt4(ra1);
            *(uint4*)&Bs[buf][b0row][b0c] = cvt4(rb0);
            *(uint4*)&Bs[buf][b1row][b1c] = cvt4(rb1);
            __syncthreads();
        }
    }

    // ---- epilogue ----
    #pragma unroll
    for (int mt=0;mt<4;mt++){
        #pragma unroll
        for (int nt=0;nt<4;nt++){
            int r0 = m0 + warpM*64 + mt*16 + gr;
            int c0 = n0 + warpN*32 + nt*8 + 2*tg;   // even
            float2 bia = *(const float2*)(bias + c0);
            #pragma unroll
            for (int half=0; half<2; ++half){
                int r = r0 + half*8;
                float v0 = acc[mt][nt][half*2+0] + bia.x;
                float v1 = acc[mt][nt][half*2+1] + bia.y;
                if (MODE == 0){
                    int which = c0 >> 9;
                    int hh = (c0 >> 6) & 7;
                    int hd = c0 & 63;
                    int bb = r >> 11;
                    int nn = r & 2047;
                    float* dst = (which == 0) ? o0 : ((which == 1) ? o1 : o2);
                    *(float2*)&dst[(((size_t)(bb*HH + hh))*NN + nn)*HDIM + hd] = make_float2(v0, v1);
                } else if (MODE == 1){
                    float2 rr = *(const float2*)(res + (size_t)r*Nn + c0);
                    *(float2*)&o0[(size_t)r*Nn + c0] = make_float2(v0 + rr.x, v1 + rr.y);
                } else {
                    float g0 = 0.5f*v0*(1.f + erff(v0*0.70710678118654752f));
                    float g1 = 0.5f*v1*(1.f + erff(v1*0.70710678118654752f));
                    *(float2*)&o0[(size_t)r*Nn + c0] = make_float2(g0, g1);
                }
            }
        }
    }
}

// ------------------------- banded rep-correlation: corr[b][off][i] = rep_i . rep_{i-R+off} -------------------------
__global__ void __launch_bounds__(256) corr_kernel(const float* __restrict__ rep, float* __restrict__ corr)
{
    __shared__ float sQ[32*36];
    __shared__ float sK[160*36];
    int b = blockIdx.x >> 6, tile = blockIdx.x & 63;
    int i0 = tile*32, j0 = i0 - RR;
    int t = threadIdx.x;
    int qi = t & 31, off0 = t >> 5;
    float acc[17];
    #pragma unroll
    for (int kk=0;kk<17;kk++) acc[kk] = 0.f;
    const float* rbase = rep + (size_t)b*NN*DD;

    for (int ch=0; ch<16; ++ch){
        int c0 = ch*32;
        {   // Q chunk: 32x32
            int row = t >> 3, c4 = (t & 7)*4;
            *(float4*)(sQ + row*36 + c4) = *(const float4*)(rbase + (size_t)(i0+row)*DD + c0 + c4);
        }
        #pragma unroll
        for (int s=0;s<5;s++){   // K chunk: 160x32
            int idx = t + s*256;
            int row = idx >> 3, c4 = (idx & 7)*4;
            int j = j0 + row;
            float4 val = make_float4(0.f,0.f,0.f,0.f);
            if (j >= 0 && j < NN) val = *(const float4*)(rbase + (size_t)j*DD + c0 + c4);
            *(float4*)(sK + row*36 + c4) = val;
        }
        __syncthreads();
        float4 qreg[8];
        #pragma unroll
        for (int c=0;c<8;c++) qreg[c] = *(const float4*)(sQ + qi*36 + c*4);
        #pragma unroll
        for (int kk=0;kk<17;kk++){
            int off = off0 + 8*kk;
            if (off > 128) break;
            const float4* k4 = (const float4*)(sK + (qi+off)*36);
            float s = acc[kk];
            #pragma unroll
            for (int c=0;c<8;c++){
                float4 kv = k4[c];
                s += qreg[c].x*kv.x + qreg[c].y*kv.y + qreg[c].z*kv.z + qreg[c].w*kv.w;
            }
            acc[kk] = s;
        }
        __syncthreads();
    }
    int i = i0 + qi;
    #pragma unroll
    for (int kk=0;kk<17;kk++){
        int off = off0 + 8*kk;
        if (off > 128) break;
        int j = j0 + qi + off;
        if (j >= 0 && j < NN)
            corr[((size_t)b*132 + off)*NN + i] = acc[kk];
    }
}

// ------------------------- banded attention -------------------------
// block = (b, h, 32-query tile); keys window = 160 rows; dyn smem 73232 B
__global__ void __launch_bounds__(256) attn_kernel(
    const float* __restrict__ q, const float* __restrict__ k, const float* __restrict__ v,
    const float* __restrict__ corr, const float* __restrict__ rel_bias,
    const float* __restrict__ rep_scale, float* __restrict__ upd)
{
    extern __shared__ float sm[];
    float* sKV   = sm;                 // 160*68
    float* sQ    = sm + 160*68;        // 32*68
    float* sS    = sQ + 32*68;         // 32*160
    float* sBias = sS + 32*160;        // 132

    int blk = blockIdx.x;
    int tile = blk & 63, h = (blk >> 6) & 7, b = blk >> 9;
    int i0 = tile*32, j0 = i0 - RR;
    int t = threadIdx.x;
    float rs = rep_scale[h];

    if (t < WW) sBias[t] = rel_bias[(size_t)(NN-1+RR - t)*HH + h];

    const float* qbase = q + ((size_t)(b*HH + h)*NN)*HDIM;
    const float* kbase = k + ((size_t)(b*HH + h)*NN)*HDIM;
    const float* vbase = v + ((size_t)(b*HH + h)*NN)*HDIM;

    #pragma unroll
    for (int s=0;s<2;s++){   // Q: 32x64
        int idx = t + s*256;
        int row = idx >> 4, c4 = (idx & 15)*4;
        *(float4*)(sQ + row*68 + c4) = *(const float4*)(qbase + (size_t)(i0+row)*HDIM + c4);
    }
    #pragma unroll
    for (int s=0;s<10;s++){  // K: 160x64, zero-fill out of range
        int idx = t + s*256;
        int row = idx >> 4, c4 = (idx & 15)*4;
        int j = j0 + row;
        float4 val = make_float4(0.f,0.f,0.f,0.f);
        if (j >= 0 && j < NN) val = *(const float4*)(kbase + (size_t)j*HDIM + c4);
        *(float4*)(sKV + row*68 + c4) = val;
    }
    float ninf = -INFINITY;
    #pragma unroll
    for (int s=0;s<20;s++) sS[t + s*256] = ninf;
    __syncthreads();

    // ---- scores ----
    {
        int qi = t & 31, off0 = t >> 5;
        int i = i0 + qi;
        float4 qreg[16];
        #pragma unroll
        for (int c=0;c<16;c++) qreg[c] = *(const float4*)(sQ + qi*68 + c*4);
        #pragma unroll
        for (int kk=0;kk<17;kk++){
            int off = off0 + 8*kk;
            if (off > 128) break;
            int l = qi + off;
            int j = j0 + l;
            if (j >= 0 && j < NN){
                const float4* k4 = (const float4*)(sKV + l*68);
                float acc = 0.f;
                #pragma unroll
                for (int c=0;c<16;c++){
                    float4 kv = k4[c];
                    acc += qreg[c].x*kv.x + qreg[c].y*kv.y + qreg[c].z*kv.z + qreg[c].w*kv.w;
                }
                sS[qi*160 + l] = acc*0.125f
                               + rs * corr[((size_t)b*132 + off)*NN + i]
                               + sBias[off];
            }
        }
    }
    __syncthreads();

    // ---- softmax (8 warps x 4 rows) ----
    {
        int w = t >> 5, lane = t & 31;
        for (int r=0;r<4;r++){
            float* row = sS + (w*4 + r)*160;
            float m = -INFINITY;
            for (int e=lane;e<160;e+=32) m = fmaxf(m, row[e]);
            #pragma unroll
            for (int o=16;o>0;o>>=1) m = fmaxf(m, __shfl_xor_sync(0xffffffffu, m, o));
            float sum = 0.f;
            for (int e=lane;e<160;e+=32){
                float p = expf(row[e] - m);
                row[e] = p;
                sum += p;
            }
            #pragma unroll
            for (int o=16;o>0;o>>=1) sum += __shfl_xor_sync(0xffffffffu, sum, o);
            float inv = 1.f / sum;
            for (int e=lane;e<160;e+=32) row[e] *= inv;
        }
    }

    // ---- load V (reuse K buffer; safe: K reads finished before pre-softmax barrier) ----
    #pragma unroll
    for (int s=0;s<10;s++){
        int idx = t + s*256;
        int row = idx >> 4, c4 = (idx & 15)*4;
        int j = j0 + row;
        float4 val = make_float4(0.f,0.f,0.f,0.f);
        if (j >= 0 && j < NN) val = *(const float4*)(vbase + (size_t)j*HDIM + c4);
        *(float4*)(sKV + row*68 + c4) = val;
    }
    __syncthreads();

    // ---- attn @ V ----
    {
        int qi = t >> 3;
        int cb = (t & 7)*4;   // cols cb and cb+32 (conflict-free)
        const float* srow = sS + qi*160;
        float4 a0 = make_float4(0.f,0.f,0.f,0.f);
        float4 a1 = make_float4(0.f,0.f,0.f,0.f);
        for (int l = qi; l <= qi + 128; ++l){
            float p = srow[l];
            float4 v0 = *(const float4*)(sKV + l*68 + cb);
            float4 v1 = *(const float4*)(sKV + l*68 + cb + 32);
            a0.x += p*v0.x; a0.y += p*v0.y; a0.z += p*v0.z; a0.w += p*v0.w;
            a1.x += p*v1.x; a1.y += p*v1.y; a1.z += p*v1.z; a1.w += p*v1.w;
        }
        float* dst = upd + ((size_t)(b*NN + i0 + qi))*DD + h*HDIM + cb;
        *(float4*)dst        = a0;
        *(float4*)(dst + 32) = a1;
    }
}

// ------------------------- host launch -------------------------
extern "C" void kernel_launch(void* const* d_in, const int* in_sizes, int n_in,
                              void* d_out, int out_size)
{
    const float* nodes     = (const float*)d_in[0];
    const float* ln1_g     = (const float*)d_in[1];
    const float* ln1_b     = (const float*)d_in[2];
    const float* qkv_w     = (const float*)d_in[3];
    const float* qkv_b     = (const float*)d_in[4];
    const float* proj_w    = (const float*)d_in[5];
    const float* proj_b    = (const float*)d_in[6];
    const float* rep_scale = (const float*)d_in[7];
    const float* rel_bias  = (const float*)d_in[8];
    const float* ln2_g     = (const float*)d_in[9];
    const float* ln2_b     = (const float*)d_in[10];
    const float* mlp_w1    = (const float*)d_in[11];
    const float* mlp_b1    = (const float*)d_in[12];
    const float* mlp_w2    = (const float*)d_in[13];
    const float* mlp_b2    = (const float*)d_in[14];
    float* out = (float*)d_out;

    float *x, *rep, *q, *k, *v, *corr, *upd, *n2, *y, *hbuf;
    cudaGetSymbolAddress((void**)&x,    g_x);
    cudaGetSymbolAddress((void**)&rep,  g_rep);
    cudaGetSymbolAddress((void**)&q,    g_q);
    cudaGetSymbolAddress((void**)&k,    g_k);
    cudaGetSymbolAddress((void**)&v,    g_v);
    cudaGetSymbolAddress((void**)&corr, g_corr);
    cudaGetSymbolAddress((void**)&upd,  g_upd);
    cudaGetSymbolAddress((void**)&n2,   g_n2);
    cudaGetSymbolAddress((void**)&y,    g_y);
    cudaGetSymbolAddress((void**)&hbuf, g_h);

    const int ATT_SMEM = (160*68 + 32*68 + 32*160 + 132) * 4;   // 73232 B
    cudaFuncSetAttribute(attn_kernel, cudaFuncAttributeMaxDynamicSharedMemorySize, ATT_SMEM);

    // 1) LN1 + rep
    ln_kernel<<<MM, 256>>>(nodes, ln1_g, ln1_b, x, rep, 1);
    // 2) QKV GEMM (4096 x 1536 x 512) with scatter epilogue  [tf32 tensor core]
    tgemm_kernel<0><<<dim3(1536/128, MM/128), 256>>>(x, qkv_w, qkv_b, nullptr, q, k, v, MM, 1536, DD);
    // 3) banded correlation
    corr_kernel<<<BB*(NN/32), 256>>>(rep, corr);
    // 4) banded attention
    attn_kernel<<<BB*HH*(NN/32), 256, ATT_SMEM>>>(q, k, v, corr, rel_bias, rep_scale, upd);
    // 5) proj + residual -> n2
    tgemm_kernel<1><<<dim3(512/128, MM/128), 256>>>(upd, proj_w, proj_b, nodes, n2, nullptr, nullptr, MM, DD, DD);
    // 6) LN2
    ln_kernel<<<MM, 256>>>(n2, ln2_g, ln2_b, y, nullptr, 0);
    // 7) MLP1 + exact GELU
    tgemm_kernel<2><<<dim3(1024/128, MM/128), 256>>>(y, mlp_w1, mlp_b1, nullptr, hbuf, nullptr, nullptr, MM, 2*DD, DD);
    // 8) MLP2 + residual -> out
    tgemm_kernel<1><<<dim3(512/128, MM/128), 256>>>(hbuf, mlp_w2, mlp_b2, n2, out, nullptr, nullptr, MM, DD, 2*DD);
}